// round 1
// baseline (speedup 1.0000x reference)
#include <cuda_runtime.h>
#include <math.h>

#define N_NODES 100000
#define N_EDGES 1600000
#define HIDDEN  48
#define ALPHA   0.1f

// Scratch (allocation-free rule: __device__ globals)
__device__ float g_x0 [N_NODES * HIDDEN];
__device__ float g_h  [N_NODES * HIDDEN];
__device__ float g_agg[N_NODES * HIDDEN];

// ---------------------------------------------------------------------------
// Init: h0 = relu(x @ W0 + b0); x0 = h0; agg = 0
// One thread per (node, channel).
// ---------------------------------------------------------------------------
__global__ void init_kernel(const float* __restrict__ x,
                            const float* __restrict__ W0,
                            const float* __restrict__ b0) {
    int idx = blockIdx.x * blockDim.x + threadIdx.x;
    if (idx >= N_NODES * HIDDEN) return;
    int n = idx / HIDDEN;
    int j = idx - n * HIDDEN;
    float v = x[n * 3 + 0] * W0[0 * HIDDEN + j]
            + x[n * 3 + 1] * W0[1 * HIDDEN + j]
            + x[n * 3 + 2] * W0[2 * HIDDEN + j]
            + b0[j];
    v = fmaxf(v, 0.0f);
    g_x0[idx]  = v;
    g_h[idx]   = v;
    g_agg[idx] = 0.0f;
}

// ---------------------------------------------------------------------------
// Scatter: agg[dst] += h[src] for every edge.
// 4 threads per edge; each thread handles 12 contiguous floats (3 x float4)
// via red.global.add.v4.f32 (no-return L2 reduction, 16B granularity).
// ---------------------------------------------------------------------------
__global__ void scatter_kernel(const int* __restrict__ ei) {
    int idx = blockIdx.x * blockDim.x + threadIdx.x;
    if (idx >= N_EDGES * 4) return;
    int e = idx >> 2;
    int q = idx & 3;
    int src = ei[e];
    int dst = ei[N_EDGES + e];

    const float4* hp = reinterpret_cast<const float4*>(g_h + (size_t)src * HIDDEN) + q * 3;
    float* ap = g_agg + (size_t)dst * HIDDEN + q * 12;

    #pragma unroll
    for (int i = 0; i < 3; i++) {
        float4 v = hp[i];
        asm volatile("red.global.add.v4.f32 [%0], {%1,%2,%3,%4};"
                     :: "l"(ap + i * 4), "f"(v.x), "f"(v.y), "f"(v.z), "f"(v.w)
                     : "memory");
    }
}

// ---------------------------------------------------------------------------
// Layer update: t = 0.9*agg + 0.1*x0 ; h = relu((1-beta)*t + beta * t@W)
// 32 nodes per block, 384 threads. convW layer slice + t tile in shared.
// Also zeroes agg in-place for the next scatter pass.
// ---------------------------------------------------------------------------
#define NPB 32
#define LTHREADS 384

__global__ __launch_bounds__(LTHREADS)
void layer_kernel(const float* __restrict__ convW, float beta) {
    __shared__ float sW[HIDDEN * HIDDEN];   // 9216 B
    __shared__ float sT[NPB * HIDDEN];      // 6144 B

    int tid = threadIdx.x;
    int base = blockIdx.x * NPB * HIDDEN;

    #pragma unroll
    for (int i = tid; i < HIDDEN * HIDDEN; i += LTHREADS)
        sW[i] = convW[i];
    #pragma unroll
    for (int i = tid; i < NPB * HIDDEN; i += LTHREADS) {
        int g = base + i;
        float a = g_agg[g];
        g_agg[g] = 0.0f;                      // reset for next propagation
        sT[i] = (1.0f - ALPHA) * a + ALPHA * g_x0[g];
    }
    __syncthreads();

    #pragma unroll
    for (int r = 0; r < (NPB * HIDDEN) / LTHREADS; r++) {
        int o = tid + r * LTHREADS;
        int n = o / HIDDEN;
        int j = o - n * HIDDEN;
        float acc = 0.0f;
        #pragma unroll
        for (int k = 0; k < HIDDEN; k++)
            acc = fmaf(sT[n * HIDDEN + k], sW[k * HIDDEN + j], acc);
        float t = sT[o];
        g_h[base + o] = fmaxf((1.0f - beta) * t + beta * acc, 0.0f);
    }
}

// ---------------------------------------------------------------------------
// Output: z = h @ W1 + b1 ; out = log_softmax(z, axis=-1)
// ---------------------------------------------------------------------------
__global__ __launch_bounds__(LTHREADS)
void out_kernel(const float* __restrict__ W1,
                const float* __restrict__ b1,
                float* __restrict__ out) {
    __shared__ float sW[HIDDEN * HIDDEN];
    __shared__ float sH[NPB * HIDDEN];
    __shared__ float sZ[NPB * HIDDEN];
    __shared__ float sM[NPB];
    __shared__ float sS[NPB];

    int tid = threadIdx.x;
    int base = blockIdx.x * NPB * HIDDEN;

    #pragma unroll
    for (int i = tid; i < HIDDEN * HIDDEN; i += LTHREADS)
        sW[i] = W1[i];
    #pragma unroll
    for (int i = tid; i < NPB * HIDDEN; i += LTHREADS)
        sH[i] = g_h[base + i];
    __syncthreads();

    #pragma unroll
    for (int r = 0; r < (NPB * HIDDEN) / LTHREADS; r++) {
        int o = tid + r * LTHREADS;
        int n = o / HIDDEN;
        int j = o - n * HIDDEN;
        float acc = b1[j];
        #pragma unroll
        for (int k = 0; k < HIDDEN; k++)
            acc = fmaf(sH[n * HIDDEN + k], sW[k * HIDDEN + j], acc);
        sZ[o] = acc;
    }
    __syncthreads();

    if (tid < NPB) {
        float m = -INFINITY;
        #pragma unroll
        for (int k = 0; k < HIDDEN; k++)
            m = fmaxf(m, sZ[tid * HIDDEN + k]);
        float s = 0.0f;
        #pragma unroll
        for (int k = 0; k < HIDDEN; k++)
            s += expf(sZ[tid * HIDDEN + k] - m);
        sM[tid] = m;
        sS[tid] = logf(s);
    }
    __syncthreads();

    #pragma unroll
    for (int r = 0; r < (NPB * HIDDEN) / LTHREADS; r++) {
        int o = tid + r * LTHREADS;
        int n = o / HIDDEN;
        out[base + o] = sZ[o] - sM[n] - sS[n];
    }
}

// ---------------------------------------------------------------------------
extern "C" void kernel_launch(void* const* d_in, const int* in_sizes, int n_in,
                              void* d_out, int out_size) {
    const float* x     = (const float*)d_in[0];
    const int*   ei    = (const int*)  d_in[1];
    const float* W0    = (const float*)d_in[2];
    const float* b0    = (const float*)d_in[3];
    const float* convW = (const float*)d_in[4];
    const float* W1    = (const float*)d_in[5];
    const float* b1    = (const float*)d_in[6];
    float* out = (float*)d_out;

    // beta_l = log(0.5/(l+1) + 1)
    const float betas[4] = {0.4054651081f, 0.2231435513f,
                            0.1541506798f, 0.1177830357f};

    const int init_threads = 256;
    const int init_blocks  = (N_NODES * HIDDEN + init_threads - 1) / init_threads;
    init_kernel<<<init_blocks, init_threads>>>(x, W0, b0);

    const int sc_threads = 256;
    const int sc_blocks  = (N_EDGES * 4 + sc_threads - 1) / sc_threads;
    const int node_blocks = N_NODES / NPB;   // 100000 / 32 = 3125

    for (int l = 0; l < 4; l++) {
        scatter_kernel<<<sc_blocks, sc_threads>>>(ei);
        layer_kernel<<<node_blocks, LTHREADS>>>(convW + l * HIDDEN * HIDDEN, betas[l]);
    }

    out_kernel<<<node_blocks, LTHREADS>>>(W1, b1, out);
}

// round 3
// speedup vs baseline: 1.2368x; 1.2368x over previous
#include <cuda_runtime.h>
#include <math.h>

#define N_NODES 100000
#define N_EDGES 1600000
#define HIDDEN  48
#define ALPHA   0.1f
#define NPB     32          // nodes per block in layer/out kernels
#define LTHREADS 384        // = NPB * 12 (one float4-lane per node)
#define SCAN_THREADS 1024

// Scratch (__device__ globals: allocation-free rule)
__device__ float g_x0 [N_NODES * HIDDEN];
__device__ float g_h  [N_NODES * HIDDEN];
__device__ float g_hb [N_NODES * HIDDEN];   // ping-pong buffer
__device__ int   g_cnt[N_NODES];
__device__ int   g_row[N_NODES + 1];
__device__ int   g_cur[N_NODES];
__device__ int   g_esrc[N_EDGES];

// ---------------------------------------------------------------------------
// Init: h0 = relu(x @ W0 + b0); x0 = h0. Also zero the degree histogram.
// ---------------------------------------------------------------------------
__global__ void init_kernel(const float* __restrict__ x,
                            const float* __restrict__ W0,
                            const float* __restrict__ b0) {
    int idx = blockIdx.x * blockDim.x + threadIdx.x;
    if (idx < N_NODES) g_cnt[idx] = 0;
    if (idx >= N_NODES * HIDDEN) return;
    int n = idx / HIDDEN;
    int j = idx - n * HIDDEN;
    float v = x[n * 3 + 0] * W0[0 * HIDDEN + j]
            + x[n * 3 + 1] * W0[1 * HIDDEN + j]
            + x[n * 3 + 2] * W0[2 * HIDDEN + j]
            + b0[j];
    v = fmaxf(v, 0.0f);
    g_x0[idx] = v;
    g_h[idx]  = v;
}

// ---------------------------------------------------------------------------
// CSR build step 1: histogram of destination degrees
// ---------------------------------------------------------------------------
__global__ void hist_kernel(const int* __restrict__ ei) {
    int e = blockIdx.x * blockDim.x + threadIdx.x;
    if (e >= N_EDGES) return;
    atomicAdd(&g_cnt[ei[N_EDGES + e]], 1);
}

// ---------------------------------------------------------------------------
// CSR build step 2: exclusive prefix sum (single block).
// ---------------------------------------------------------------------------
__global__ __launch_bounds__(SCAN_THREADS)
void scan_kernel() {
    __shared__ int sSum[SCAN_THREADS];
    const int CHUNK = (N_NODES + SCAN_THREADS - 1) / SCAN_THREADS;  // 98
    int tid = threadIdx.x;
    int start = tid * CHUNK;
    int end = min(start + CHUNK, N_NODES);

    int s = 0;
    for (int i = start; i < end; i++) s += g_cnt[i];
    sSum[tid] = s;
    __syncthreads();

    for (int off = 1; off < SCAN_THREADS; off <<= 1) {
        int v = (tid >= off) ? sSum[tid - off] : 0;
        __syncthreads();
        sSum[tid] += v;
        __syncthreads();
    }

    int run = (tid == 0) ? 0 : sSum[tid - 1];
    for (int i = start; i < end; i++) {
        int c = g_cnt[i];
        g_row[i] = run;
        g_cur[i] = run;
        run += c;
    }
    if (tid == SCAN_THREADS - 1) g_row[N_NODES] = run;
}

// ---------------------------------------------------------------------------
// CSR build step 3: fill edge source lists
// ---------------------------------------------------------------------------
__global__ void fill_kernel(const int* __restrict__ ei) {
    int e = blockIdx.x * blockDim.x + threadIdx.x;
    if (e >= N_EDGES) return;
    int dst = ei[N_EDGES + e];
    int pos = atomicAdd(&g_cur[dst], 1);
    g_esrc[pos] = ei[e];
}

// ---------------------------------------------------------------------------
// Fused layer: gather (pull) + residual mix + 48x48 GEMM + relu.
// flip=0: read g_h, write g_hb.  flip=1: read g_hb, write g_h.
// ---------------------------------------------------------------------------
__global__ __launch_bounds__(LTHREADS)
void layer_fused(const float* __restrict__ convW, float beta, int flip) {
    __shared__ float sW[HIDDEN * HIDDEN];   // 9216 B
    __shared__ float sT[NPB * HIDDEN];      // 6144 B

    const float* __restrict__ hin  = flip ? g_hb : g_h;
    float*       __restrict__ hout = flip ? g_h  : g_hb;

    int tid = threadIdx.x;
    int node_local = tid / 12;
    int q = tid - node_local * 12;          // which float4 of the 48-row
    int node = blockIdx.x * NPB + node_local;
    int base = blockIdx.x * NPB * HIDDEN;

    #pragma unroll
    for (int i = tid; i < HIDDEN * HIDDEN; i += LTHREADS)
        sW[i] = convW[i];

    int rs = g_row[node];
    int re = g_row[node + 1];
    float4 acc = make_float4(0.f, 0.f, 0.f, 0.f);
    for (int j = rs; j < re; j++) {
        int src = g_esrc[j];            // 12 threads same addr -> broadcast
        float4 v = *(reinterpret_cast<const float4*>(hin + (size_t)src * HIDDEN) + q);
        acc.x += v.x; acc.y += v.y; acc.z += v.z; acc.w += v.w;
    }
    float4 x0v = *(reinterpret_cast<const float4*>(g_x0 + (size_t)node * HIDDEN) + q);
    float4 t;
    t.x = (1.0f - ALPHA) * acc.x + ALPHA * x0v.x;
    t.y = (1.0f - ALPHA) * acc.y + ALPHA * x0v.y;
    t.z = (1.0f - ALPHA) * acc.z + ALPHA * x0v.z;
    t.w = (1.0f - ALPHA) * acc.w + ALPHA * x0v.w;
    *(reinterpret_cast<float4*>(sT + node_local * HIDDEN) + q) = t;
    __syncthreads();

    #pragma unroll
    for (int r = 0; r < (NPB * HIDDEN) / LTHREADS; r++) {
        int o = tid + r * LTHREADS;
        int n = o / HIDDEN;
        int j = o - n * HIDDEN;
        float a = 0.0f;
        #pragma unroll
        for (int k = 0; k < HIDDEN; k++)
            a = fmaf(sT[n * HIDDEN + k], sW[k * HIDDEN + j], a);
        float tv = sT[o];
        hout[base + o] = fmaxf((1.0f - beta) * tv + beta * a, 0.0f);
    }
}

// ---------------------------------------------------------------------------
// Output: z = h @ W1 + b1 ; out = log_softmax(z)   (reads g_h)
// ---------------------------------------------------------------------------
__global__ __launch_bounds__(LTHREADS)
void out_kernel(const float* __restrict__ W1,
                const float* __restrict__ b1,
                float* __restrict__ out) {
    __shared__ float sW[HIDDEN * HIDDEN];
    __shared__ float sH[NPB * HIDDEN];
    __shared__ float sZ[NPB * HIDDEN];
    __shared__ float sM[NPB];
    __shared__ float sS[NPB];

    int tid = threadIdx.x;
    int base = blockIdx.x * NPB * HIDDEN;

    #pragma unroll
    for (int i = tid; i < HIDDEN * HIDDEN; i += LTHREADS)
        sW[i] = W1[i];
    #pragma unroll
    for (int i = tid; i < NPB * HIDDEN; i += LTHREADS)
        sH[i] = g_h[base + i];
    __syncthreads();

    #pragma unroll
    for (int r = 0; r < (NPB * HIDDEN) / LTHREADS; r++) {
        int o = tid + r * LTHREADS;
        int n = o / HIDDEN;
        int j = o - n * HIDDEN;
        float a = b1[j];
        #pragma unroll
        for (int k = 0; k < HIDDEN; k++)
            a = fmaf(sH[n * HIDDEN + k], sW[k * HIDDEN + j], a);
        sZ[o] = a;
    }
    __syncthreads();

    if (tid < NPB) {
        float m = -INFINITY;
        #pragma unroll
        for (int k = 0; k < HIDDEN; k++)
            m = fmaxf(m, sZ[tid * HIDDEN + k]);
        float s = 0.0f;
        #pragma unroll
        for (int k = 0; k < HIDDEN; k++)
            s += expf(sZ[tid * HIDDEN + k] - m);
        sM[tid] = m;
        sS[tid] = logf(s);
    }
    __syncthreads();

    #pragma unroll
    for (int r = 0; r < (NPB * HIDDEN) / LTHREADS; r++) {
        int o = tid + r * LTHREADS;
        int n = o / HIDDEN;
        out[base + o] = sZ[o] - sM[n] - sS[n];
    }
}

// ---------------------------------------------------------------------------
extern "C" void kernel_launch(void* const* d_in, const int* in_sizes, int n_in,
                              void* d_out, int out_size) {
    const float* x     = (const float*)d_in[0];
    const int*   ei    = (const int*)  d_in[1];
    const float* W0    = (const float*)d_in[2];
    const float* b0    = (const float*)d_in[3];
    const float* convW = (const float*)d_in[4];
    const float* W1    = (const float*)d_in[5];
    const float* b1    = (const float*)d_in[6];
    float* out = (float*)d_out;

    // beta_l = log(0.5/(l+1) + 1)
    const float betas[4] = {0.4054651081f, 0.2231435513f,
                            0.1541506798f, 0.1177830357f};

    const int it = 256;
    init_kernel<<<(N_NODES * HIDDEN + it - 1) / it, it>>>(x, W0, b0);

    const int et = 256;
    const int eb = (N_EDGES + et - 1) / et;
    hist_kernel<<<eb, et>>>(ei);
    scan_kernel<<<1, SCAN_THREADS>>>();
    fill_kernel<<<eb, et>>>(ei);

    const int node_blocks = N_NODES / NPB;   // 3125
    for (int l = 0; l < 4; l++)
        layer_fused<<<node_blocks, LTHREADS>>>(convW + l * HIDDEN * HIDDEN,
                                               betas[l], l & 1);

    // layers 0..3: h path g_h -> g_hb -> g_h -> g_hb -> g_h (final in g_h)
    out_kernel<<<node_blocks, LTHREADS>>>(W1, b1, out);
}

// round 4
// speedup vs baseline: 1.2405x; 1.0030x over previous
#include <cuda_runtime.h>
#include <math.h>

#define N_NODES 100000
#define N_EDGES 1600000
#define HIDDEN  48
#define ALPHA   0.1f
#define NPB     32          // nodes per block in layer/out kernels
#define LTHREADS 384        // = NPB * 12 (one float4-lane per node)
#define ECAP    1024        // smem edge-index buffer per block
#define SCAN_THREADS 1024

// Scratch (__device__ globals: allocation-free rule)
__device__ float g_x0 [N_NODES * HIDDEN];
__device__ float g_h  [N_NODES * HIDDEN];
__device__ float g_hb [N_NODES * HIDDEN];   // ping-pong buffer
__device__ int   g_cnt[N_NODES];
__device__ int   g_row[N_NODES + 1];
__device__ int   g_cur[N_NODES];
__device__ int   g_esrc[N_EDGES];

// ---------------------------------------------------------------------------
// Init: h0 = relu(x @ W0 + b0); x0 = h0. Also zero the degree histogram.
// ---------------------------------------------------------------------------
__global__ void init_kernel(const float* __restrict__ x,
                            const float* __restrict__ W0,
                            const float* __restrict__ b0) {
    int idx = blockIdx.x * blockDim.x + threadIdx.x;
    if (idx < N_NODES) g_cnt[idx] = 0;
    if (idx >= N_NODES * HIDDEN) return;
    int n = idx / HIDDEN;
    int j = idx - n * HIDDEN;
    float v = x[n * 3 + 0] * W0[0 * HIDDEN + j]
            + x[n * 3 + 1] * W0[1 * HIDDEN + j]
            + x[n * 3 + 2] * W0[2 * HIDDEN + j]
            + b0[j];
    v = fmaxf(v, 0.0f);
    g_x0[idx] = v;
    g_h[idx]  = v;
}

// ---------------------------------------------------------------------------
// CSR build step 1: histogram of destination degrees
// ---------------------------------------------------------------------------
__global__ void hist_kernel(const int* __restrict__ ei) {
    int e = blockIdx.x * blockDim.x + threadIdx.x;
    if (e >= N_EDGES) return;
    atomicAdd(&g_cnt[ei[N_EDGES + e]], 1);
}

// ---------------------------------------------------------------------------
// CSR build step 2: exclusive prefix sum (single block).
// ---------------------------------------------------------------------------
__global__ __launch_bounds__(SCAN_THREADS)
void scan_kernel() {
    __shared__ int sSum[SCAN_THREADS];
    const int CHUNK = (N_NODES + SCAN_THREADS - 1) / SCAN_THREADS;  // 98
    int tid = threadIdx.x;
    int start = tid * CHUNK;
    int end = min(start + CHUNK, N_NODES);

    int s = 0;
    for (int i = start; i < end; i++) s += g_cnt[i];
    sSum[tid] = s;
    __syncthreads();

    for (int off = 1; off < SCAN_THREADS; off <<= 1) {
        int v = (tid >= off) ? sSum[tid - off] : 0;
        __syncthreads();
        sSum[tid] += v;
        __syncthreads();
    }

    int run = (tid == 0) ? 0 : sSum[tid - 1];
    for (int i = start; i < end; i++) {
        int c = g_cnt[i];
        g_row[i] = run;
        g_cur[i] = run;
        run += c;
    }
    if (tid == SCAN_THREADS - 1) g_row[N_NODES] = run;
}

// ---------------------------------------------------------------------------
// CSR build step 3: fill edge source lists
// ---------------------------------------------------------------------------
__global__ void fill_kernel(const int* __restrict__ ei) {
    int e = blockIdx.x * blockDim.x + threadIdx.x;
    if (e >= N_EDGES) return;
    int dst = ei[N_EDGES + e];
    int pos = atomicAdd(&g_cur[dst], 1);
    g_esrc[pos] = ei[e];
}

// ---------------------------------------------------------------------------
// Fused layer: gather (pull, smem-staged indices, 4x unrolled) + residual mix
// + 48x48 GEMM + relu.
// flip=0: read g_h, write g_hb.  flip=1: read g_hb, write g_h.
// ---------------------------------------------------------------------------
__global__ __launch_bounds__(LTHREADS)
void layer_fused(const float* __restrict__ convW, float beta, int flip) {
    __shared__ float sW[HIDDEN * HIDDEN];   // 9216 B
    __shared__ float sT[NPB * HIDDEN];      // 6144 B
    __shared__ int   sE[ECAP];              // 4096 B

    const float* __restrict__ hin  = flip ? g_hb : g_h;
    float*       __restrict__ hout = flip ? g_h  : g_hb;

    int tid = threadIdx.x;
    int node_local = tid / 12;
    int q = tid - node_local * 12;          // which float4 of the 48-row
    int node = blockIdx.x * NPB + node_local;
    int base = blockIdx.x * NPB * HIDDEN;

    #pragma unroll
    for (int i = tid; i < HIDDEN * HIDDEN; i += LTHREADS)
        sW[i] = convW[i];

    // Block's edge slice is contiguous in CSR: stage indices into shared.
    int eStart = g_row[blockIdx.x * NPB];
    int eEnd   = g_row[blockIdx.x * NPB + NPB];
    int eCount = eEnd - eStart;
    if (eCount <= ECAP) {
        for (int i = tid; i < eCount; i += LTHREADS)
            sE[i] = g_esrc[eStart + i];
    }
    __syncthreads();

    int rs = g_row[node]     - eStart;
    int re = g_row[node + 1] - eStart;

    float4 acc = make_float4(0.f, 0.f, 0.f, 0.f);

#define GATHER4(IDX0, IDX1, IDX2, IDX3)                                          \
    {                                                                            \
        float4 v0 = *(reinterpret_cast<const float4*>(hin + (size_t)(IDX0) * HIDDEN) + q); \
        float4 v1 = *(reinterpret_cast<const float4*>(hin + (size_t)(IDX1) * HIDDEN) + q); \
        float4 v2 = *(reinterpret_cast<const float4*>(hin + (size_t)(IDX2) * HIDDEN) + q); \
        float4 v3 = *(reinterpret_cast<const float4*>(hin + (size_t)(IDX3) * HIDDEN) + q); \
        acc.x += v0.x + v1.x + v2.x + v3.x;                                      \
        acc.y += v0.y + v1.y + v2.y + v3.y;                                      \
        acc.z += v0.z + v1.z + v2.z + v3.z;                                      \
        acc.w += v0.w + v1.w + v2.w + v3.w;                                      \
    }

    if (eCount <= ECAP) {
        int j = rs;
        for (; j + 4 <= re; j += 4) {
            int s0 = sE[j], s1 = sE[j + 1], s2 = sE[j + 2], s3 = sE[j + 3];
            GATHER4(s0, s1, s2, s3);
        }
        for (; j < re; j++) {
            int s = sE[j];
            float4 v = *(reinterpret_cast<const float4*>(hin + (size_t)s * HIDDEN) + q);
            acc.x += v.x; acc.y += v.y; acc.z += v.z; acc.w += v.w;
        }
    } else {
        const int* ge = g_esrc + eStart;
        int j = rs;
        for (; j + 4 <= re; j += 4) {
            int s0 = ge[j], s1 = ge[j + 1], s2 = ge[j + 2], s3 = ge[j + 3];
            GATHER4(s0, s1, s2, s3);
        }
        for (; j < re; j++) {
            int s = ge[j];
            float4 v = *(reinterpret_cast<const float4*>(hin + (size_t)s * HIDDEN) + q);
            acc.x += v.x; acc.y += v.y; acc.z += v.z; acc.w += v.w;
        }
    }
#undef GATHER4

    float4 x0v = *(reinterpret_cast<const float4*>(g_x0 + (size_t)node * HIDDEN) + q);
    float4 t;
    t.x = (1.0f - ALPHA) * acc.x + ALPHA * x0v.x;
    t.y = (1.0f - ALPHA) * acc.y + ALPHA * x0v.y;
    t.z = (1.0f - ALPHA) * acc.z + ALPHA * x0v.z;
    t.w = (1.0f - ALPHA) * acc.w + ALPHA * x0v.w;
    *(reinterpret_cast<float4*>(sT + node_local * HIDDEN) + q) = t;
    __syncthreads();

    #pragma unroll
    for (int r = 0; r < (NPB * HIDDEN) / LTHREADS; r++) {
        int o = tid + r * LTHREADS;
        int n = o / HIDDEN;
        int j = o - n * HIDDEN;
        float a = 0.0f;
        #pragma unroll
        for (int k = 0; k < HIDDEN; k++)
            a = fmaf(sT[n * HIDDEN + k], sW[k * HIDDEN + j], a);
        float tv = sT[o];
        hout[base + o] = fmaxf((1.0f - beta) * tv + beta * a, 0.0f);
    }
}

// ---------------------------------------------------------------------------
// Output: z = h @ W1 + b1 ; out = log_softmax(z)   (reads g_h)
// ---------------------------------------------------------------------------
__global__ __launch_bounds__(LTHREADS)
void out_kernel(const float* __restrict__ W1,
                const float* __restrict__ b1,
                float* __restrict__ out) {
    __shared__ float sW[HIDDEN * HIDDEN];
    __shared__ float sH[NPB * HIDDEN];
    __shared__ float sZ[NPB * HIDDEN];
    __shared__ float sM[NPB];
    __shared__ float sS[NPB];

    int tid = threadIdx.x;
    int base = blockIdx.x * NPB * HIDDEN;

    #pragma unroll
    for (int i = tid; i < HIDDEN * HIDDEN; i += LTHREADS)
        sW[i] = W1[i];
    #pragma unroll
    for (int i = tid; i < NPB * HIDDEN; i += LTHREADS)
        sH[i] = g_h[base + i];
    __syncthreads();

    #pragma unroll
    for (int r = 0; r < (NPB * HIDDEN) / LTHREADS; r++) {
        int o = tid + r * LTHREADS;
        int n = o / HIDDEN;
        int j = o - n * HIDDEN;
        float a = b1[j];
        #pragma unroll
        for (int k = 0; k < HIDDEN; k++)
            a = fmaf(sH[n * HIDDEN + k], sW[k * HIDDEN + j], a);
        sZ[o] = a;
    }
    __syncthreads();

    if (tid < NPB) {
        float m = -INFINITY;
        #pragma unroll
        for (int k = 0; k < HIDDEN; k++)
            m = fmaxf(m, sZ[tid * HIDDEN + k]);
        float s = 0.0f;
        #pragma unroll
        for (int k = 0; k < HIDDEN; k++)
            s += expf(sZ[tid * HIDDEN + k] - m);
        sM[tid] = m;
        sS[tid] = logf(s);
    }
    __syncthreads();

    #pragma unroll
    for (int r = 0; r < (NPB * HIDDEN) / LTHREADS; r++) {
        int o = tid + r * LTHREADS;
        int n = o / HIDDEN;
        out[base + o] = sZ[o] - sM[n] - sS[n];
    }
}

// ---------------------------------------------------------------------------
extern "C" void kernel_launch(void* const* d_in, const int* in_sizes, int n_in,
                              void* d_out, int out_size) {
    const float* x     = (const float*)d_in[0];
    const int*   ei    = (const int*)  d_in[1];
    const float* W0    = (const float*)d_in[2];
    const float* b0    = (const float*)d_in[3];
    const float* convW = (const float*)d_in[4];
    const float* W1    = (const float*)d_in[5];
    const float* b1    = (const float*)d_in[6];
    float* out = (float*)d_out;

    // beta_l = log(0.5/(l+1) + 1)
    const float betas[4] = {0.4054651081f, 0.2231435513f,
                            0.1541506798f, 0.1177830357f};

    const int it = 256;
    init_kernel<<<(N_NODES * HIDDEN + it - 1) / it, it>>>(x, W0, b0);

    const int et = 256;
    const int eb = (N_EDGES + et - 1) / et;
    hist_kernel<<<eb, et>>>(ei);
    scan_kernel<<<1, SCAN_THREADS>>>();
    fill_kernel<<<eb, et>>>(ei);

    const int node_blocks = N_NODES / NPB;   // 3125
    for (int l = 0; l < 4; l++)
        layer_fused<<<node_blocks, LTHREADS>>>(convW + l * HIDDEN * HIDDEN,
                                               betas[l], l & 1);

    // layers 0..3: h path g_h -> g_hb -> g_h -> g_hb -> g_h (final in g_h)
    out_kernel<<<node_blocks, LTHREADS>>>(W1, b1, out);
}

// round 5
// speedup vs baseline: 1.9110x; 1.5405x over previous
#include <cuda_runtime.h>
#include <math.h>

#define N_NODES 100000
#define N_EDGES 1600000
#define HIDDEN  48
#define ALPHA   0.1f
#define NPB     160         // nodes per block (100000 = 625 * 160)
#define LTHREADS 192        // 48 gather groups of 4; GEMM: 16 m-slots x 12 quads
#define ECAP    3584        // smem edge-index buffer (mean 2560, sigma ~51)
#define SCB     100         // scan blocks
#define SCHUNK  1000        // elements per scan block

// Scratch (__device__ globals: allocation-free rule)
__device__ float g_x0 [N_NODES * HIDDEN];
__device__ float g_h  [N_NODES * HIDDEN];
__device__ float g_hb [N_NODES * HIDDEN];   // ping-pong buffer
__device__ int   g_cnt[N_NODES];
__device__ int   g_row[N_NODES + 1];
__device__ int   g_cur[N_NODES];
__device__ int   g_esrc[N_EDGES];
__device__ int   g_part[SCB];

// ---------------------------------------------------------------------------
// Init: h0 = relu(x @ W0 + b0); x0 = h0. Also zero the degree histogram.
// ---------------------------------------------------------------------------
__global__ void init_kernel(const float* __restrict__ x,
                            const float* __restrict__ W0,
                            const float* __restrict__ b0) {
    int idx = blockIdx.x * blockDim.x + threadIdx.x;
    if (idx < N_NODES) g_cnt[idx] = 0;
    if (idx >= N_NODES * HIDDEN) return;
    int n = idx / HIDDEN;
    int j = idx - n * HIDDEN;
    float v = x[n * 3 + 0] * W0[0 * HIDDEN + j]
            + x[n * 3 + 1] * W0[1 * HIDDEN + j]
            + x[n * 3 + 2] * W0[2 * HIDDEN + j]
            + b0[j];
    v = fmaxf(v, 0.0f);
    g_x0[idx] = v;
    g_h[idx]  = v;
}

// ---------------------------------------------------------------------------
// CSR build: histogram of destination degrees
// ---------------------------------------------------------------------------
__global__ void hist_kernel(const int* __restrict__ ei) {
    int e = blockIdx.x * blockDim.x + threadIdx.x;
    if (e >= N_EDGES) return;
    atomicAdd(&g_cnt[ei[N_EDGES + e]], 1);
}

// ---------------------------------------------------------------------------
// Parallel exclusive scan over g_cnt: A (block sums) -> B (combine) -> C (final)
// ---------------------------------------------------------------------------
__global__ __launch_bounds__(256) void scanA_kernel() {
    __shared__ int s[256];
    int b = blockIdx.x, t = threadIdx.x;
    int sum = 0;
    for (int i = t; i < SCHUNK; i += 256) sum += g_cnt[b * SCHUNK + i];
    s[t] = sum;
    __syncthreads();
    for (int off = 128; off > 0; off >>= 1) {
        if (t < off) s[t] += s[t + off];
        __syncthreads();
    }
    if (t == 0) g_part[b] = s[0];
}

__global__ __launch_bounds__(128) void scanB_kernel() {
    __shared__ int sp[SCB];
    int t = threadIdx.x;
    if (t < SCB) sp[t] = g_part[t];
    __syncthreads();
    if (t == 0) {
        int run = 0;
        for (int i = 0; i < SCB; i++) { int c = sp[i]; sp[i] = run; run += c; }
        g_row[N_NODES] = run;
    }
    __syncthreads();
    if (t < SCB) g_part[t] = sp[t];
}

__global__ __launch_bounds__(1024) void scanC_kernel() {
    __shared__ int s[1024];
    int b = blockIdx.x, t = threadIdx.x;
    int i = b * SCHUNK + t;
    int c = (t < SCHUNK) ? g_cnt[i] : 0;
    s[t] = c;
    __syncthreads();
    for (int off = 1; off < 1024; off <<= 1) {
        int v = (t >= off) ? s[t - off] : 0;
        __syncthreads();
        s[t] += v;
        __syncthreads();
    }
    if (t < SCHUNK) {
        int excl = s[t] - c + g_part[b];
        g_row[i] = excl;
        g_cur[i] = excl;
    }
}

// ---------------------------------------------------------------------------
// CSR build: fill edge source lists
// ---------------------------------------------------------------------------
__global__ void fill_kernel(const int* __restrict__ ei) {
    int e = blockIdx.x * blockDim.x + threadIdx.x;
    if (e >= N_EDGES) return;
    int dst = ei[N_EDGES + e];
    int pos = atomicAdd(&g_cur[dst], 1);
    g_esrc[pos] = ei[e];
}

// ---------------------------------------------------------------------------
// float4 helpers
// ---------------------------------------------------------------------------
__device__ __forceinline__ void f4add(float4& a, const float4& b) {
    a.x += b.x; a.y += b.y; a.z += b.z; a.w += b.w;
}
__device__ __forceinline__ void f4add2(float4& a, const float4& b, const float4& c) {
    a.x += b.x + c.x; a.y += b.y + c.y; a.z += b.z + c.z; a.w += b.w + c.w;
}

// ---------------------------------------------------------------------------
// Fused layer: balanced gather (4-lane groups, dynamic node claiming)
// + residual mix + register-blocked 48x48 GEMM + relu.
// flip=0: read g_h, write g_hb.  flip=1: read g_hb, write g_h.
// ---------------------------------------------------------------------------
__global__ __launch_bounds__(LTHREADS)
void layer_fused(const float* __restrict__ convW, float beta, int flip) {
    __shared__ float sW[HIDDEN * HIDDEN];   // 9216 B
    __shared__ float sT[NPB * HIDDEN];      // 30720 B
    __shared__ int   sE[ECAP];              // 14336 B
    __shared__ int   sR[NPB + 1];           // 644 B
    __shared__ int   sClaim;

    const float* __restrict__ hin  = flip ? g_hb : g_h;
    float*       __restrict__ hout = flip ? g_h  : g_hb;

    int tid = threadIdx.x;
    int node0 = blockIdx.x * NPB;

    #pragma unroll
    for (int i = tid; i < HIDDEN * HIDDEN; i += LTHREADS)
        sW[i] = convW[i];
    for (int i = tid; i <= NPB; i += LTHREADS)
        sR[i] = g_row[node0 + i];

    int eStart = g_row[node0];
    int eCount = g_row[node0 + NPB] - eStart;
    bool inSmem = (eCount <= ECAP);
    if (inSmem) {
        for (int i = tid; i < eCount; i += LTHREADS)
            sE[i] = g_esrc[eStart + i];
    }
    if (tid == 0) sClaim = 0;
    __syncthreads();

    // --- balanced gather: groups of 4 lanes claim nodes dynamically ---
    int lane = tid & 31;
    int c = tid & 3;                          // lane owns floats [12c, 12c+12)
    unsigned submask = 0xFu << (lane & ~3);

    while (true) {
        int n = 0;
        if (c == 0) n = atomicAdd(&sClaim, 1);
        n = __shfl_sync(submask, n, 0, 4);
        if (n >= NPB) break;

        int rs = sR[n], re = sR[n + 1];
        float4 a0 = make_float4(0.f, 0.f, 0.f, 0.f);
        float4 a1 = a0, a2 = a0;

        if (inSmem) {
            int j = rs - eStart, je = re - eStart;
            for (; j + 2 <= je; j += 2) {
                int s0 = sE[j], s1 = sE[j + 1];
                const float4* p0 = reinterpret_cast<const float4*>(hin + (size_t)s0 * HIDDEN) + 3 * c;
                const float4* p1 = reinterpret_cast<const float4*>(hin + (size_t)s1 * HIDDEN) + 3 * c;
                float4 u0 = p0[0], u1 = p0[1], u2 = p0[2];
                float4 w0 = p1[0], w1 = p1[1], w2 = p1[2];
                f4add2(a0, u0, w0); f4add2(a1, u1, w1); f4add2(a2, u2, w2);
            }
            if (j < je) {
                int s0 = sE[j];
                const float4* p0 = reinterpret_cast<const float4*>(hin + (size_t)s0 * HIDDEN) + 3 * c;
                f4add(a0, p0[0]); f4add(a1, p0[1]); f4add(a2, p0[2]);
            }
        } else {
            const int* ge = g_esrc;
            int j = rs;
            for (; j + 2 <= re; j += 2) {
                int s0 = ge[j], s1 = ge[j + 1];
                const float4* p0 = reinterpret_cast<const float4*>(hin + (size_t)s0 * HIDDEN) + 3 * c;
                const float4* p1 = reinterpret_cast<const float4*>(hin + (size_t)s1 * HIDDEN) + 3 * c;
                float4 u0 = p0[0], u1 = p0[1], u2 = p0[2];
                float4 w0 = p1[0], w1 = p1[1], w2 = p1[2];
                f4add2(a0, u0, w0); f4add2(a1, u1, w1); f4add2(a2, u2, w2);
            }
            if (j < re) {
                int s0 = ge[j];
                const float4* p0 = reinterpret_cast<const float4*>(hin + (size_t)s0 * HIDDEN) + 3 * c;
                f4add(a0, p0[0]); f4add(a1, p0[1]); f4add(a2, p0[2]);
            }
        }

        const float4* px = reinterpret_cast<const float4*>(g_x0 + (size_t)(node0 + n) * HIDDEN) + 3 * c;
        float4 x0v0 = px[0], x0v1 = px[1], x0v2 = px[2];
        float4 t0, t1, t2;
        t0.x = (1.0f - ALPHA) * a0.x + ALPHA * x0v0.x;
        t0.y = (1.0f - ALPHA) * a0.y + ALPHA * x0v0.y;
        t0.z = (1.0f - ALPHA) * a0.z + ALPHA * x0v0.z;
        t0.w = (1.0f - ALPHA) * a0.w + ALPHA * x0v0.w;
        t1.x = (1.0f - ALPHA) * a1.x + ALPHA * x0v1.x;
        t1.y = (1.0f - ALPHA) * a1.y + ALPHA * x0v1.y;
        t1.z = (1.0f - ALPHA) * a1.z + ALPHA * x0v1.z;
        t1.w = (1.0f - ALPHA) * a1.w + ALPHA * x0v1.w;
        t2.x = (1.0f - ALPHA) * a2.x + ALPHA * x0v2.x;
        t2.y = (1.0f - ALPHA) * a2.y + ALPHA * x0v2.y;
        t2.z = (1.0f - ALPHA) * a2.z + ALPHA * x0v2.z;
        t2.w = (1.0f - ALPHA) * a2.w + ALPHA * x0v2.w;
        float4* pt = reinterpret_cast<float4*>(sT + n * HIDDEN) + 3 * c;
        pt[0] = t0; pt[1] = t1; pt[2] = t2;
    }
    __syncthreads();

    // --- register-blocked GEMM: thread (q, m) does quad q of 10 nodes ---
    int q = tid % 12;          // output quad
    int m = tid / 12;          // 0..15; nodes m, m+16, ..., m+144
    const float4* sW4 = reinterpret_cast<const float4*>(sW);

    float4 acc[10];
    #pragma unroll
    for (int i = 0; i < 10; i++) acc[i] = make_float4(0.f, 0.f, 0.f, 0.f);

    for (int k = 0; k < HIDDEN; k++) {
        float4 w = sW4[k * 12 + q];
        #pragma unroll
        for (int i = 0; i < 10; i++) {
            float a = sT[(m + 16 * i) * HIDDEN + k];
            acc[i].x = fmaf(a, w.x, acc[i].x);
            acc[i].y = fmaf(a, w.y, acc[i].y);
            acc[i].z = fmaf(a, w.z, acc[i].z);
            acc[i].w = fmaf(a, w.w, acc[i].w);
        }
    }

    float ob = 1.0f - beta;
    #pragma unroll
    for (int i = 0; i < 10; i++) {
        int n = m + 16 * i;
        float4 t = *(reinterpret_cast<const float4*>(sT + n * HIDDEN) + q);
        float4 o;
        o.x = fmaxf(ob * t.x + beta * acc[i].x, 0.0f);
        o.y = fmaxf(ob * t.y + beta * acc[i].y, 0.0f);
        o.z = fmaxf(ob * t.z + beta * acc[i].z, 0.0f);
        o.w = fmaxf(ob * t.w + beta * acc[i].w, 0.0f);
        *(reinterpret_cast<float4*>(hout + (size_t)(node0 + n) * HIDDEN) + q) = o;
    }
}

// ---------------------------------------------------------------------------
// Output: z = h @ W1 + b1 ; out = log_softmax(z)   (reads g_h)
// ---------------------------------------------------------------------------
__global__ __launch_bounds__(LTHREADS)
void out_kernel(const float* __restrict__ W1,
                const float* __restrict__ b1,
                float* __restrict__ out) {
    __shared__ float sW[HIDDEN * HIDDEN];
    __shared__ float sT[NPB * HIDDEN];
    __shared__ float sZ[NPB * HIDDEN];
    __shared__ float sLS[NPB];

    int tid = threadIdx.x;
    int node0 = blockIdx.x * NPB;
    int base = node0 * HIDDEN;

    #pragma unroll
    for (int i = tid; i < HIDDEN * HIDDEN; i += LTHREADS)
        sW[i] = W1[i];
    {
        const float4* gh4 = reinterpret_cast<const float4*>(g_h + base);
        float4* sT4 = reinterpret_cast<float4*>(sT);
        for (int i = tid; i < NPB * HIDDEN / 4; i += LTHREADS)
            sT4[i] = gh4[i];
    }
    __syncthreads();

    int q = tid % 12;
    int m = tid / 12;
    const float4* sW4 = reinterpret_cast<const float4*>(sW);
    float4 bv = reinterpret_cast<const float4*>(b1)[q];

    float4 acc[10];
    #pragma unroll
    for (int i = 0; i < 10; i++) acc[i] = bv;

    for (int k = 0; k < HIDDEN; k++) {
        float4 w = sW4[k * 12 + q];
        #pragma unroll
        for (int i = 0; i < 10; i++) {
            float a = sT[(m + 16 * i) * HIDDEN + k];
            acc[i].x = fmaf(a, w.x, acc[i].x);
            acc[i].y = fmaf(a, w.y, acc[i].y);
            acc[i].z = fmaf(a, w.z, acc[i].z);
            acc[i].w = fmaf(a, w.w, acc[i].w);
        }
    }
    #pragma unroll
    for (int i = 0; i < 10; i++) {
        int n = m + 16 * i;
        *(reinterpret_cast<float4*>(sZ + n * HIDDEN) + q) = acc[i];
    }
    __syncthreads();

    if (tid < NPB) {
        float mx = -INFINITY;
        #pragma unroll
        for (int k = 0; k < HIDDEN; k++)
            mx = fmaxf(mx, sZ[tid * HIDDEN + k]);
        float s = 0.0f;
        #pragma unroll
        for (int k = 0; k < HIDDEN; k++)
            s += expf(sZ[tid * HIDDEN + k] - mx);
        sLS[tid] = mx + logf(s);
    }
    __syncthreads();

    #pragma unroll
    for (int i = 0; i < 10; i++) {
        int n = m + 16 * i;
        float ls = sLS[n];
        float4 z = *(reinterpret_cast<const float4*>(sZ + n * HIDDEN) + q);
        float4 o;
        o.x = z.x - ls; o.y = z.y - ls; o.z = z.z - ls; o.w = z.w - ls;
        *(reinterpret_cast<float4*>(out + (size_t)base + n * HIDDEN) + q) = o;
    }
}

// ---------------------------------------------------------------------------
extern "C" void kernel_launch(void* const* d_in, const int* in_sizes, int n_in,
                              void* d_out, int out_size) {
    const float* x     = (const float*)d_in[0];
    const int*   ei    = (const int*)  d_in[1];
    const float* W0    = (const float*)d_in[2];
    const float* b0    = (const float*)d_in[3];
    const float* convW = (const float*)d_in[4];
    const float* W1    = (const float*)d_in[5];
    const float* b1    = (const float*)d_in[6];
    float* out = (float*)d_out;

    // beta_l = log(0.5/(l+1) + 1)
    const float betas[4] = {0.4054651081f, 0.2231435513f,
                            0.1541506798f, 0.1177830357f};

    const int it = 256;
    init_kernel<<<(N_NODES * HIDDEN + it - 1) / it, it>>>(x, W0, b0);

    const int et = 256;
    const int eb = (N_EDGES + et - 1) / et;
    hist_kernel<<<eb, et>>>(ei);
    scanA_kernel<<<SCB, 256>>>();
    scanB_kernel<<<1, 128>>>();
    scanC_kernel<<<SCB, 1024>>>();
    fill_kernel<<<eb, et>>>(ei);

    const int node_blocks = N_NODES / NPB;   // 625
    for (int l = 0; l < 4; l++)
        layer_fused<<<node_blocks, LTHREADS>>>(convW + l * HIDDEN * HIDDEN,
                                               betas[l], l & 1);

    // layers 0..3: h path g_h -> g_hb -> g_h -> g_hb -> g_h (final in g_h)
    out_kernel<<<node_blocks, LTHREADS>>>(W1, b1, out);
}